// round 1
// baseline (speedup 1.0000x reference)
#include <cuda_runtime.h>

// Global scratch accumulators: [0]=S_pos, [1]=S_neg, [2]=count_pos, [3]=count_neg
__device__ double g_acc[4];

__global__ void el_init_kernel() {
    if (threadIdx.x < 4) g_acc[threadIdx.x] = 0.0;
}

__global__ void __launch_bounds__(256) el_reduce_kernel(
    const float4* __restrict__ x4, const float4* __restrict__ t4, int n4)
{
    float s_pos = 0.0f, s_neg = 0.0f, c_pos = 0.0f, c_neg = 0.0f;

    int idx    = blockIdx.x * blockDim.x + threadIdx.x;
    int stride = gridDim.x * blockDim.x;

    for (int i = idx; i < n4; i += stride) {
        float4 xv = x4[i];
        float4 tv = t4[i];

        float xs[4] = {xv.x, xv.y, xv.z, xv.w};
        float ts[4] = {tv.x, tv.y, tv.z, tv.w};

        #pragma unroll
        for (int k = 0; k < 4; k++) {
            float x = xs[k];
            float t = ts[k];
            float a = fabsf(x);
            // log1p(exp(-a)) with fast-math; abs error <= ~6e-8, fine for 1e-3 budget
            float l = __logf(1.0f + __expf(-a));
            float base = fmaxf(x, 0.0f) + l;     // bce for t==0
            bool p = (t == 1.0f);
            bool n = (t == 0.0f);
            s_pos += p ? (base - x) : 0.0f;      // bce for t==1: max(x,0) - x + l
            s_neg += n ? base       : 0.0f;
            c_pos += p ? 1.0f : 0.0f;
            c_neg += n ? 1.0f : 0.0f;
        }
    }

    // Warp reduction of the 4 partials
    #pragma unroll
    for (int off = 16; off > 0; off >>= 1) {
        s_pos += __shfl_xor_sync(0xFFFFFFFF, s_pos, off);
        s_neg += __shfl_xor_sync(0xFFFFFFFF, s_neg, off);
        c_pos += __shfl_xor_sync(0xFFFFFFFF, c_pos, off);
        c_neg += __shfl_xor_sync(0xFFFFFFFF, c_neg, off);
    }

    __shared__ float sh[4][8];   // 8 warps per 256-thread block
    int wid = threadIdx.x >> 5;
    int lid = threadIdx.x & 31;

    if (lid == 0) {
        sh[0][wid] = s_pos;
        sh[1][wid] = s_neg;
        sh[2][wid] = c_pos;
        sh[3][wid] = c_neg;
    }
    __syncthreads();

    if (wid == 0) {
        float v0 = (lid < 8) ? sh[0][lid] : 0.0f;
        float v1 = (lid < 8) ? sh[1][lid] : 0.0f;
        float v2 = (lid < 8) ? sh[2][lid] : 0.0f;
        float v3 = (lid < 8) ? sh[3][lid] : 0.0f;
        #pragma unroll
        for (int off = 4; off > 0; off >>= 1) {
            v0 += __shfl_xor_sync(0xFFFFFFFF, v0, off);
            v1 += __shfl_xor_sync(0xFFFFFFFF, v1, off);
            v2 += __shfl_xor_sync(0xFFFFFFFF, v2, off);
            v3 += __shfl_xor_sync(0xFFFFFFFF, v3, off);
        }
        if (lid == 0) {
            atomicAdd(&g_acc[0], (double)v0);
            atomicAdd(&g_acc[1], (double)v1);
            atomicAdd(&g_acc[2], (double)v2);
            atomicAdd(&g_acc[3], (double)v3);
        }
    }
}

__global__ void el_final_kernel(float* __restrict__ out, double inv_n) {
    double Sp = g_acc[0];
    double Sn = g_acc[1];
    double Cp = g_acc[2];
    double Cn = g_acc[3];
    double denom = Cp + Cn;
    // mean over ALL n elements of w*bce, where
    // w = Cn/denom on positives, Cp/denom on negatives, 0 on ignore
    double r = (Cn * Sp + Cp * Sn) / denom * inv_n;
    out[0] = (float)r;
}

extern "C" void kernel_launch(void* const* d_in, const int* in_sizes, int n_in,
                              void* d_out, int out_size) {
    const float* x = (const float*)d_in[0];
    const float* t = (const float*)d_in[1];
    float* out = (float*)d_out;

    int n  = in_sizes[0];
    int n4 = n >> 2;   // n = 25,165,824 is divisible by 4

    el_init_kernel<<<1, 32>>>();

    const int threads = 256;
    int blocks = 148 * 16;   // 2368 blocks, grid-stride covers n4
    int max_blocks = (n4 + threads - 1) / threads;
    if (blocks > max_blocks) blocks = max_blocks;

    el_reduce_kernel<<<blocks, threads>>>(
        (const float4*)x, (const float4*)t, n4);

    el_final_kernel<<<1, 1>>>(out, 1.0 / (double)n);
}

// round 2
// speedup vs baseline: 1.0269x; 1.0269x over previous
#include <cuda_runtime.h>

// Per-block partials: (S_pos, S_neg, C_pos, C_neg). Overwritten every launch.
#define MAX_BLOCKS 2048
__device__ float4 g_partials[MAX_BLOCKS];
__device__ unsigned int g_count;   // zero-initialized; last-block atomicInc wraps it back to 0

__device__ __forceinline__ void bce_accum(float x, float t,
                                          float& s_pos, float& s_neg,
                                          float& c_pos, float& c_neg)
{
    float a = fabsf(x);
    float l = __logf(1.0f + __expf(-a));   // log1p(exp(-|x|)), fast-math
    float base = fmaxf(x, 0.0f) + l;       // bce when t==0
    bool p = (t == 1.0f);
    bool n = (t == 0.0f);
    s_pos += p ? (base - x) : 0.0f;        // bce when t==1
    s_neg += n ? base       : 0.0f;
    c_pos += p ? 1.0f : 0.0f;
    c_neg += n ? 1.0f : 0.0f;
}

__global__ void __launch_bounds__(256) el_fused_kernel(
    const float4* __restrict__ x4, const float4* __restrict__ t4,
    int n4, float* __restrict__ out, double inv_n)
{
    float s_pos = 0.0f, s_neg = 0.0f, c_pos = 0.0f, c_neg = 0.0f;

    int tid    = blockIdx.x * blockDim.x + threadIdx.x;
    int stride = gridDim.x * blockDim.x;

    // Unroll-by-4 main loop: front-batch 8 independent float4 loads (MLP ~8)
    int i = tid;
    for (; i + 3 * stride < n4; i += 4 * stride) {
        float4 xa = __ldcs(&x4[i]);
        float4 xb = __ldcs(&x4[i + stride]);
        float4 xc = __ldcs(&x4[i + 2 * stride]);
        float4 xd = __ldcs(&x4[i + 3 * stride]);
        float4 ta = __ldcs(&t4[i]);
        float4 tb = __ldcs(&t4[i + stride]);
        float4 tc = __ldcs(&t4[i + 2 * stride]);
        float4 td = __ldcs(&t4[i + 3 * stride]);

        bce_accum(xa.x, ta.x, s_pos, s_neg, c_pos, c_neg);
        bce_accum(xa.y, ta.y, s_pos, s_neg, c_pos, c_neg);
        bce_accum(xa.z, ta.z, s_pos, s_neg, c_pos, c_neg);
        bce_accum(xa.w, ta.w, s_pos, s_neg, c_pos, c_neg);
        bce_accum(xb.x, tb.x, s_pos, s_neg, c_pos, c_neg);
        bce_accum(xb.y, tb.y, s_pos, s_neg, c_pos, c_neg);
        bce_accum(xb.z, tb.z, s_pos, s_neg, c_pos, c_neg);
        bce_accum(xb.w, tb.w, s_pos, s_neg, c_pos, c_neg);
        bce_accum(xc.x, tc.x, s_pos, s_neg, c_pos, c_neg);
        bce_accum(xc.y, tc.y, s_pos, s_neg, c_pos, c_neg);
        bce_accum(xc.z, tc.z, s_pos, s_neg, c_pos, c_neg);
        bce_accum(xc.w, tc.w, s_pos, s_neg, c_pos, c_neg);
        bce_accum(xd.x, td.x, s_pos, s_neg, c_pos, c_neg);
        bce_accum(xd.y, td.y, s_pos, s_neg, c_pos, c_neg);
        bce_accum(xd.z, td.z, s_pos, s_neg, c_pos, c_neg);
        bce_accum(xd.w, td.w, s_pos, s_neg, c_pos, c_neg);
    }
    for (; i < n4; i += stride) {
        float4 xv = __ldcs(&x4[i]);
        float4 tv = __ldcs(&t4[i]);
        bce_accum(xv.x, tv.x, s_pos, s_neg, c_pos, c_neg);
        bce_accum(xv.y, tv.y, s_pos, s_neg, c_pos, c_neg);
        bce_accum(xv.z, tv.z, s_pos, s_neg, c_pos, c_neg);
        bce_accum(xv.w, tv.w, s_pos, s_neg, c_pos, c_neg);
    }

    // Intra-warp reduction
    #pragma unroll
    for (int off = 16; off > 0; off >>= 1) {
        s_pos += __shfl_xor_sync(0xFFFFFFFF, s_pos, off);
        s_neg += __shfl_xor_sync(0xFFFFFFFF, s_neg, off);
        c_pos += __shfl_xor_sync(0xFFFFFFFF, c_pos, off);
        c_neg += __shfl_xor_sync(0xFFFFFFFF, c_neg, off);
    }

    __shared__ float4 sh[8];
    int wid = threadIdx.x >> 5;
    int lid = threadIdx.x & 31;
    if (lid == 0) sh[wid] = make_float4(s_pos, s_neg, c_pos, c_neg);
    __syncthreads();

    __shared__ bool s_is_last;
    if (threadIdx.x == 0) {
        float4 acc = sh[0];
        #pragma unroll
        for (int w = 1; w < 8; w++) {
            float4 v = sh[w];
            acc.x += v.x; acc.y += v.y; acc.z += v.z; acc.w += v.w;
        }
        g_partials[blockIdx.x] = acc;
        __threadfence();
        // atomicInc wraps to 0 when old == gridDim.x-1 -> counter self-resets (graph-safe)
        unsigned int old = atomicInc(&g_count, gridDim.x - 1);
        s_is_last = (old == gridDim.x - 1);
    }
    __syncthreads();

    // Last block: reduce per-block partials and finalize
    if (s_is_last) {
        float p0 = 0.0f, p1 = 0.0f, p2 = 0.0f, p3 = 0.0f;
        for (int b = threadIdx.x; b < gridDim.x; b += blockDim.x) {
            float4 v = g_partials[b];
            p0 += v.x; p1 += v.y; p2 += v.z; p3 += v.w;
        }
        #pragma unroll
        for (int off = 16; off > 0; off >>= 1) {
            p0 += __shfl_xor_sync(0xFFFFFFFF, p0, off);
            p1 += __shfl_xor_sync(0xFFFFFFFF, p1, off);
            p2 += __shfl_xor_sync(0xFFFFFFFF, p2, off);
            p3 += __shfl_xor_sync(0xFFFFFFFF, p3, off);
        }
        __shared__ float4 sh2[8];
        if (lid == 0) sh2[wid] = make_float4(p0, p1, p2, p3);
        __syncthreads();
        if (threadIdx.x == 0) {
            double Sp = 0.0, Sn = 0.0, Cp = 0.0, Cn = 0.0;
            #pragma unroll
            for (int w = 0; w < 8; w++) {
                float4 v = sh2[w];
                Sp += v.x; Sn += v.y; Cp += v.z; Cn += v.w;
            }
            double denom = Cp + Cn;
            out[0] = (float)((Cn * Sp + Cp * Sn) / denom * inv_n);
        }
    }
}

extern "C" void kernel_launch(void* const* d_in, const int* in_sizes, int n_in,
                              void* d_out, int out_size) {
    const float* x = (const float*)d_in[0];
    const float* t = (const float*)d_in[1];
    float* out = (float*)d_out;

    int n  = in_sizes[0];
    int n4 = n >> 2;   // n = 25,165,824 divisible by 4

    const int threads = 256;
    int blocks = 148 * 8;   // one resident wave
    int max_blocks = (n4 + threads - 1) / threads;
    if (blocks > max_blocks) blocks = max_blocks;
    if (blocks > MAX_BLOCKS) blocks = MAX_BLOCKS;

    el_fused_kernel<<<blocks, threads>>>(
        (const float4*)x, (const float4*)t, n4, out, 1.0 / (double)n);
}